// round 1
// baseline (speedup 1.0000x reference)
#include <cuda_runtime.h>
#include <math.h>

// Problem constants
#define BB 16
#define NN 2048
#define TT 48
#define EE 32
#define CC 64
#define H1 256
#define H2 128
#define NPRED 12
#define SEQS (BB * NN)          // 32768
#define PITCH 65                // smem row pitch for [48][64] tiles (conflict-free)

#define GRID_A 1024
#define GRID_B (SEQS / 32)      // 1024 blocks, 32 rows each

// Scratch: attention output "last" vectors (32768 x 64 floats = 8 MB)
__device__ float g_last[SEQS * CC];

// ---------------------------------------------------------------------------
// Kernel A: fused  input-proj -> conv1d(k=3,pad=1)+relu -> K,V proj ->
//           Q(last row only) -> softmax(last row) -> ctx(last row)
// One block = 256 threads; weights cached in smem once per block; grid-stride
// over sequences.
// ---------------------------------------------------------------------------
struct SmemA {
    float W_in[EE * CC];        // 2048
    float b_in[CC];
    float Wc[3 * CC * CC];      // 12288
    float b_conv[CC];
    float Wq[CC * CC];          // 4096
    float Wk[CC * CC];
    float Wv[CC * CC];
    float bq[CC], bk[CC], bv[CC];
    float x[TT * EE];           // 1536
    float h0p[(TT + 2) * PITCH];// padded rows: 0 and 49 stay zero
    float hc[TT * PITCH];
    float k[TT * PITCH];
    float v[TT * PITCH];
    float q[CC];
    float score[TT];
    float expv[TT];
};

__global__ __launch_bounds__(256, 1)
void fused_frontend_kernel(const float* __restrict__ x,
                           const float* __restrict__ W_in, const float* __restrict__ b_in,
                           const float* __restrict__ Wc,   const float* __restrict__ b_conv,
                           const float* __restrict__ Wq,   const float* __restrict__ bq,
                           const float* __restrict__ Wk,   const float* __restrict__ bk,
                           const float* __restrict__ Wv,   const float* __restrict__ bv)
{
    extern __shared__ float smem_raw[];
    SmemA& sm = *reinterpret_cast<SmemA*>(smem_raw);
    const int tid = threadIdx.x;

    // ---- load weights once per block ----
    for (int i = tid; i < EE * CC; i += 256) sm.W_in[i] = W_in[i];
    for (int i = tid; i < 3 * CC * CC; i += 256) sm.Wc[i] = Wc[i];
    for (int i = tid; i < CC * CC; i += 256) {
        sm.Wq[i] = Wq[i]; sm.Wk[i] = Wk[i]; sm.Wv[i] = Wv[i];
    }
    if (tid < CC) {
        sm.b_in[tid] = b_in[tid]; sm.b_conv[tid] = b_conv[tid];
        sm.bq[tid] = bq[tid]; sm.bk[tid] = bk[tid]; sm.bv[tid] = bv[tid];
    }
    // zero conv padding rows (stay zero across all sequences)
    for (int i = tid; i < PITCH; i += 256) {
        sm.h0p[i] = 0.0f;
        sm.h0p[(TT + 1) * PITCH + i] = 0.0f;
    }

    const int c  = tid & 63;        // channel / output column
    const int tg = tid >> 6;        // 0..3 time group
    const int t0 = tg * 12;         // 12 time steps per group

    for (int s = blockIdx.x; s < SEQS; s += gridDim.x) {
        __syncthreads();   // previous iteration fully consumed

        // ---- load x[s] : 48x32 ----
        const float* xp = x + (size_t)s * (TT * EE);
        for (int i = tid; i < TT * EE; i += 256) sm.x[i] = xp[i];
        __syncthreads();

        // ---- step 1: h0 = x @ W_in + b_in  (write into padded buffer) ----
        {
            float acc[12];
            float bi = sm.b_in[c];
            #pragma unroll
            for (int j = 0; j < 12; j++) acc[j] = bi;
            #pragma unroll 4
            for (int e = 0; e < EE; e++) {
                float w = sm.W_in[e * CC + c];
                #pragma unroll
                for (int j = 0; j < 12; j++)
                    acc[j] += sm.x[(t0 + j) * EE + e] * w;
            }
            #pragma unroll
            for (int j = 0; j < 12; j++)
                sm.h0p[(t0 + j + 1) * PITCH + c] = acc[j];
        }
        __syncthreads();

        // ---- step 2: conv1d (k=3, pad=1) + bias + relu ----
        {
            float acc[12];
            float bc = sm.b_conv[c];
            #pragma unroll
            for (int j = 0; j < 12; j++) acc[j] = bc;
            for (int c0 = 0; c0 < CC; c0++) {
                float w0 = sm.Wc[(0 * CC + c0) * CC + c];
                float w1 = sm.Wc[(1 * CC + c0) * CC + c];
                float w2 = sm.Wc[(2 * CC + c0) * CC + c];
                float h[14];
                #pragma unroll
                for (int j = 0; j < 14; j++)
                    h[j] = sm.h0p[(t0 + j) * PITCH + c0];
                #pragma unroll
                for (int j = 0; j < 12; j++)
                    acc[j] += h[j] * w0 + h[j + 1] * w1 + h[j + 2] * w2;
            }
            #pragma unroll
            for (int j = 0; j < 12; j++)
                sm.hc[(t0 + j) * PITCH + c] = fmaxf(acc[j], 0.0f);
        }
        __syncthreads();

        // ---- step 3: K, V projections (and Q for last row by tg==0) ----
        {
            float ak[12], av[12];
            float bkv = sm.bk[c], bvv = sm.bv[c];
            #pragma unroll
            for (int j = 0; j < 12; j++) { ak[j] = bkv; av[j] = bvv; }
            for (int c0 = 0; c0 < CC; c0++) {
                float wk = sm.Wk[c0 * CC + c];
                float wv = sm.Wv[c0 * CC + c];
                #pragma unroll
                for (int j = 0; j < 12; j++) {
                    float hv = sm.hc[(t0 + j) * PITCH + c0];
                    ak[j] += hv * wk;
                    av[j] += hv * wv;
                }
            }
            #pragma unroll
            for (int j = 0; j < 12; j++) {
                sm.k[(t0 + j) * PITCH + c] = ak[j];
                sm.v[(t0 + j) * PITCH + c] = av[j];
            }
            if (tg == 0) {
                float a = sm.bq[c];
                #pragma unroll 8
                for (int c0 = 0; c0 < CC; c0++)
                    a += sm.hc[(TT - 1) * PITCH + c0] * sm.Wq[c0 * CC + c];
                sm.q[c] = a;
            }
        }
        __syncthreads();

        // ---- step 4: attention, last row only ----
        if (tid < TT) {
            float sc = 0.0f;
            #pragma unroll 8
            for (int d = 0; d < CC; d++)
                sc += sm.q[d] * sm.k[tid * PITCH + d];
            sm.score[tid] = sc * 0.125f;   // / sqrt(64)
        }
        __syncthreads();
        if (tid < TT) {
            float m = -1e30f;
            #pragma unroll 8
            for (int i = 0; i < TT; i++) m = fmaxf(m, sm.score[i]);
            sm.expv[tid] = __expf(sm.score[tid] - m);
        }
        __syncthreads();
        if (tid < CC) {
            float ssum = 0.0f, o = 0.0f;
            #pragma unroll 8
            for (int i = 0; i < TT; i++) {
                float e = sm.expv[i];
                ssum += e;
                o += e * sm.v[i * PITCH + tid];
            }
            g_last[(size_t)s * CC + tid] = o / ssum;
        }
    }
}

// ---------------------------------------------------------------------------
// Kernel B: MLP   last(64) -> relu(256) -> relu(128) -> 12, + output transpose
// Each block handles 32 rows; z1/z2 staged in smem; weights streamed from L2.
// ---------------------------------------------------------------------------
struct SmemB {
    float last[32 * CC];        // 2048
    float z1[32 * H1];          // 8192
    float z2[32 * (H2 + 1)];    // 4128 (pitch 129: conflict-free final GEMV)
};

__global__ __launch_bounds__(256)
void mlp_kernel(const float* __restrict__ W1, const float* __restrict__ b1,
                const float* __restrict__ W2, const float* __restrict__ b2,
                const float* __restrict__ W3, const float* __restrict__ b3,
                float* __restrict__ out)
{
    extern __shared__ float smem_raw[];
    SmemB& sm = *reinterpret_cast<SmemB*>(smem_raw);
    const int tid = threadIdx.x;
    const int row0 = blockIdx.x * 32;

    for (int i = tid; i < 32 * CC; i += 256)
        sm.last[i] = g_last[(size_t)row0 * CC + i];
    __syncthreads();

    // z1 = relu(last @ W1 + b1) : thread = output column h (256 cols)
    {
        const int h = tid;
        float acc[32];
        float bb = b1[h];
        #pragma unroll
        for (int r = 0; r < 32; r++) acc[r] = bb;
        for (int cin = 0; cin < CC; cin++) {
            float w = W1[cin * H1 + h];
            #pragma unroll
            for (int r = 0; r < 32; r++)
                acc[r] += sm.last[r * CC + cin] * w;
        }
        #pragma unroll
        for (int r = 0; r < 32; r++)
            sm.z1[r * H1 + h] = fmaxf(acc[r], 0.0f);
    }
    __syncthreads();

    // z2 = relu(z1 @ W2 + b2) : thread = (h2, row-half)
    {
        const int h2 = tid & 127;
        const int rg = tid >> 7;        // 0 or 1 -> rows rg*16 .. rg*16+15
        float acc[16];
        float bb = b2[h2];
        #pragma unroll
        for (int r = 0; r < 16; r++) acc[r] = bb;
        for (int cin = 0; cin < H1; cin++) {
            float w = W2[cin * H2 + h2];
            #pragma unroll
            for (int r = 0; r < 16; r++)
                acc[r] += sm.z1[(rg * 16 + r) * H1 + cin] * w;
        }
        #pragma unroll
        for (int r = 0; r < 16; r++)
            sm.z2[(rg * 16 + r) * (H2 + 1) + h2] = fmaxf(acc[r], 0.0f);
    }
    __syncthreads();

    // pred = z2 @ W3 + b3, then scatter to out[b][0][p][n]
    for (int o = tid; o < 32 * NPRED; o += 256) {
        int r = o / NPRED;
        int p = o - r * NPRED;
        float a = b3[p];
        #pragma unroll 8
        for (int kk = 0; kk < H2; kk++)
            a += sm.z2[r * (H2 + 1) + kk] * W3[kk * NPRED + p];
        int g = row0 + r;
        int b = g >> 11;           // / 2048
        int n = g & 2047;
        out[((size_t)b * NPRED + p) * NN + n] = a;
    }
}

// ---------------------------------------------------------------------------
extern "C" void kernel_launch(void* const* d_in, const int* in_sizes, int n_in,
                              void* d_out, int out_size)
{
    (void)in_sizes; (void)n_in; (void)out_size;
    const float* x      = (const float*)d_in[0];
    const float* W_in   = (const float*)d_in[1];
    const float* b_in   = (const float*)d_in[2];
    const float* W_conv = (const float*)d_in[3];
    const float* b_conv = (const float*)d_in[4];
    const float* Wq     = (const float*)d_in[5];
    const float* bq     = (const float*)d_in[6];
    const float* Wk     = (const float*)d_in[7];
    const float* bk     = (const float*)d_in[8];
    const float* Wv     = (const float*)d_in[9];
    const float* bv     = (const float*)d_in[10];
    const float* W1     = (const float*)d_in[11];
    const float* b1     = (const float*)d_in[12];
    const float* W2     = (const float*)d_in[13];
    const float* b2     = (const float*)d_in[14];
    const float* W3     = (const float*)d_in[15];
    const float* b3     = (const float*)d_in[16];
    float* out = (float*)d_out;

    cudaFuncSetAttribute(fused_frontend_kernel,
                         cudaFuncAttributeMaxDynamicSharedMemorySize,
                         (int)sizeof(SmemA));
    cudaFuncSetAttribute(mlp_kernel,
                         cudaFuncAttributeMaxDynamicSharedMemorySize,
                         (int)sizeof(SmemB));

    fused_frontend_kernel<<<GRID_A, 256, sizeof(SmemA)>>>(
        x, W_in, b_in, W_conv, b_conv, Wq, bq, Wk, bk, Wv, bv);
    mlp_kernel<<<GRID_B, 256, sizeof(SmemB)>>>(W1, b1, W2, b2, W3, b3, out);
}

// round 2
// speedup vs baseline: 1.2541x; 1.2541x over previous
#include <cuda_runtime.h>
#include <math.h>

// Problem constants
#define BB 16
#define NN 2048
#define TT 48
#define EE 32
#define CC 64
#define H1 256
#define H2 128
#define NPRED 12
#define SEQS (BB * NN)          // 32768

#define GRID_A 2048             // 16 seqs per block
#define GRID_B (SEQS / 32)      // 1024 blocks, 32 rows each

#define PD 128                  // pitch (floats) of duplicated [48][64] tiles
#define PK 66                   // pitch of K buffer (2-way conflict on score GEMV)

typedef unsigned long long u64;

// packed fp32x2 helpers (Blackwell FFMA2 — only reachable via PTX)
__device__ __forceinline__ u64 ffma2(u64 a, u64 b, u64 c) {
    u64 d; asm("fma.rn.f32x2 %0, %1, %2, %3;" : "=l"(d) : "l"(a), "l"(b), "l"(c)); return d;
}
__device__ __forceinline__ u64 pack2(float x, float y) {
    u64 d; asm("mov.b64 %0, {%1, %2};" : "=l"(d) : "f"(x), "f"(y)); return d;
}
__device__ __forceinline__ float2 unpack2(u64 v) {
    float2 r; asm("mov.b64 {%0, %1}, %2;" : "=f"(r.x), "=f"(r.y) : "l"(v)); return r;
}
__device__ __forceinline__ u64 lds64(const float* p) { return *reinterpret_cast<const u64*>(p); }
__device__ __forceinline__ void sts64(float* p, u64 v) { *reinterpret_cast<u64*>(p) = v; }

// Scratch: attention output "last" vectors (32768 x 64 floats = 8 MB)
__device__ float g_last[SEQS * CC];

// ---------------------------------------------------------------------------
// Kernel A: fused  input-proj -> conv1d(k=3,pad=1)+relu -> K,V proj ->
//           Q(last row) -> softmax(last row) -> ctx(last row)
// 512 threads; thread = (channel-pair cp: channels 2cp,2cp+1, time-group tg: 3 steps)
// Activations stored DUPLICATED in smem so broadcast LDS.64 yields packed ops.
// ---------------------------------------------------------------------------
struct SmemA {
    float W_in[EE * CC];        // 2048
    float Wc[3 * CC * CC];      // 12288
    float Wq[CC * CC];          // 4096
    float Wk[CC * CC];          // 4096
    float Wv[CC * CC];          // 4096
    float b_in[CC], b_conv[CC], bq[CC], bk[CC], bv[CC];
    float xd[TT * 2 * EE];      // 3072  x duplicated over e: [t][2e],(x,x)
    float h0d[(TT + 2) * PD];   // 6400  padded+duplicated
    float hcd[TT * PD];         // 6144  duplicated
    float kbuf[TT * PK];        // 3168
    float vbuf[TT * CC];        // 3072
    float q[CC];
    float score[TT];
    float expv[TT];
};

__global__ __launch_bounds__(512, 1)
void fused_frontend_kernel(const float* __restrict__ x,
                           const float* __restrict__ W_in, const float* __restrict__ b_in,
                           const float* __restrict__ Wc,   const float* __restrict__ b_conv,
                           const float* __restrict__ Wq,   const float* __restrict__ bq,
                           const float* __restrict__ Wk,   const float* __restrict__ bk,
                           const float* __restrict__ Wv,   const float* __restrict__ bv)
{
    extern __shared__ float smem_raw[];
    SmemA& sm = *reinterpret_cast<SmemA*>(smem_raw);
    const int tid = threadIdx.x;

    // ---- load weights once per block ----
    for (int i = tid; i < EE * CC; i += 512) sm.W_in[i] = W_in[i];
    for (int i = tid; i < 3 * CC * CC; i += 512) sm.Wc[i] = Wc[i];
    for (int i = tid; i < CC * CC; i += 512) {
        sm.Wq[i] = Wq[i]; sm.Wk[i] = Wk[i]; sm.Wv[i] = Wv[i];
    }
    if (tid < CC) {
        sm.b_in[tid] = b_in[tid]; sm.b_conv[tid] = b_conv[tid];
        sm.bq[tid] = bq[tid]; sm.bk[tid] = bk[tid]; sm.bv[tid] = bv[tid];
    }
    // zero conv padding rows (stay zero forever)
    for (int i = tid; i < PD; i += 512) {
        sm.h0d[i] = 0.0f;
        sm.h0d[(TT + 1) * PD + i] = 0.0f;
    }

    const int cp = tid & 31;        // channel pair -> channels 2cp, 2cp+1
    const int tg = tid >> 5;        // 0..15
    const int t0 = tg * 3;          // 3 time steps per thread

    for (int s = blockIdx.x; s < SEQS; s += GRID_A) {
        __syncthreads();   // previous iteration fully consumed

        // ---- load x[s] (48x32), store duplicated over e ----
        {
            const float* xp = x + (size_t)s * (TT * EE);
            #pragma unroll
            for (int rep = 0; rep < 3; rep++) {
                int i = rep * 512 + tid;        // 1536 total
                float v = xp[i];
                int t = i >> 5, e = i & 31;
                sts64(&sm.xd[t * (2 * EE) + 2 * e], pack2(v, v));
            }
        }
        __syncthreads();

        // ---- step 1: h0 = x @ W_in + b_in  (write duplicated, padded) ----
        {
            u64 acc0, acc1, acc2;
            {
                u64 bi = lds64(&sm.b_in[2 * cp]);
                acc0 = bi; acc1 = bi; acc2 = bi;
            }
            #pragma unroll 8
            for (int e = 0; e < EE; e++) {
                u64 w = lds64(&sm.W_in[e * CC + 2 * cp]);
                acc0 = ffma2(lds64(&sm.xd[(t0 + 0) * (2 * EE) + 2 * e]), w, acc0);
                acc1 = ffma2(lds64(&sm.xd[(t0 + 1) * (2 * EE) + 2 * e]), w, acc1);
                acc2 = ffma2(lds64(&sm.xd[(t0 + 2) * (2 * EE) + 2 * e]), w, acc2);
            }
            #pragma unroll
            for (int j = 0; j < 3; j++) {
                float2 a = unpack2(j == 0 ? acc0 : (j == 1 ? acc1 : acc2));
                float* row = &sm.h0d[(t0 + j + 1) * PD + 4 * cp];
                sts64(row,     pack2(a.x, a.x));
                sts64(row + 2, pack2(a.y, a.y));
            }
        }
        __syncthreads();

        // ---- step 2: conv1d (k=3, pad=1) + bias + relu (write duplicated) ----
        {
            u64 acc0, acc1, acc2;
            {
                u64 bc = lds64(&sm.b_conv[2 * cp]);
                acc0 = bc; acc1 = bc; acc2 = bc;
            }
            #pragma unroll 4
            for (int c0 = 0; c0 < CC; c0++) {
                u64 w0 = lds64(&sm.Wc[(0 * CC + c0) * CC + 2 * cp]);
                u64 w1 = lds64(&sm.Wc[(1 * CC + c0) * CC + 2 * cp]);
                u64 w2 = lds64(&sm.Wc[(2 * CC + c0) * CC + 2 * cp]);
                u64 h0v = lds64(&sm.h0d[(t0 + 0) * PD + 2 * c0]);
                u64 h1v = lds64(&sm.h0d[(t0 + 1) * PD + 2 * c0]);
                u64 h2v = lds64(&sm.h0d[(t0 + 2) * PD + 2 * c0]);
                u64 h3v = lds64(&sm.h0d[(t0 + 3) * PD + 2 * c0]);
                u64 h4v = lds64(&sm.h0d[(t0 + 4) * PD + 2 * c0]);
                acc0 = ffma2(h0v, w0, acc0); acc0 = ffma2(h1v, w1, acc0); acc0 = ffma2(h2v, w2, acc0);
                acc1 = ffma2(h1v, w0, acc1); acc1 = ffma2(h2v, w1, acc1); acc1 = ffma2(h3v, w2, acc1);
                acc2 = ffma2(h2v, w0, acc2); acc2 = ffma2(h3v, w1, acc2); acc2 = ffma2(h4v, w2, acc2);
            }
            #pragma unroll
            for (int j = 0; j < 3; j++) {
                float2 a = unpack2(j == 0 ? acc0 : (j == 1 ? acc1 : acc2));
                float r0 = fmaxf(a.x, 0.0f), r1 = fmaxf(a.y, 0.0f);
                float* row = &sm.hcd[(t0 + j) * PD + 4 * cp];
                sts64(row,     pack2(r0, r0));
                sts64(row + 2, pack2(r1, r1));
            }
        }
        __syncthreads();

        // ---- step 3: K, V projections (Q for last row by warp 0) ----
        {
            u64 ak0, ak1, ak2, av0, av1, av2;
            {
                u64 bkk = lds64(&sm.bk[2 * cp]);
                u64 bvv = lds64(&sm.bv[2 * cp]);
                ak0 = bkk; ak1 = bkk; ak2 = bkk;
                av0 = bvv; av1 = bvv; av2 = bvv;
            }
            #pragma unroll 4
            for (int c0 = 0; c0 < CC; c0++) {
                u64 wk = lds64(&sm.Wk[c0 * CC + 2 * cp]);
                u64 wv = lds64(&sm.Wv[c0 * CC + 2 * cp]);
                u64 h0v = lds64(&sm.hcd[(t0 + 0) * PD + 2 * c0]);
                u64 h1v = lds64(&sm.hcd[(t0 + 1) * PD + 2 * c0]);
                u64 h2v = lds64(&sm.hcd[(t0 + 2) * PD + 2 * c0]);
                ak0 = ffma2(h0v, wk, ak0); av0 = ffma2(h0v, wv, av0);
                ak1 = ffma2(h1v, wk, ak1); av1 = ffma2(h1v, wv, av1);
                ak2 = ffma2(h2v, wk, ak2); av2 = ffma2(h2v, wv, av2);
            }
            sts64(&sm.kbuf[(t0 + 0) * PK + 2 * cp], ak0);
            sts64(&sm.kbuf[(t0 + 1) * PK + 2 * cp], ak1);
            sts64(&sm.kbuf[(t0 + 2) * PK + 2 * cp], ak2);
            sts64(&sm.vbuf[(t0 + 0) * CC + 2 * cp], av0);
            sts64(&sm.vbuf[(t0 + 1) * CC + 2 * cp], av1);
            sts64(&sm.vbuf[(t0 + 2) * CC + 2 * cp], av2);

            if (tg == 0) {   // Q for last row, packed over channel pair
                u64 aq = lds64(&sm.bq[2 * cp]);
                #pragma unroll 8
                for (int c0 = 0; c0 < CC; c0++) {
                    u64 h = lds64(&sm.hcd[(TT - 1) * PD + 2 * c0]);
                    u64 w = lds64(&sm.Wq[c0 * CC + 2 * cp]);
                    aq = ffma2(h, w, aq);
                }
                sts64(&sm.q[2 * cp], aq);
            }
        }
        __syncthreads();

        // ---- step 4: attention scores (last row), packed dot products ----
        if (tid < TT) {
            u64 sc2 = 0;   // (0.0f, 0.0f)
            #pragma unroll 8
            for (int d2 = 0; d2 < CC / 2; d2++) {
                u64 kv = lds64(&sm.kbuf[tid * PK + 2 * d2]);
                u64 qv = lds64(&sm.q[2 * d2]);
                sc2 = ffma2(kv, qv, sc2);
            }
            float2 p = unpack2(sc2);
            sm.score[tid] = (p.x + p.y) * 0.125f;   // / sqrt(64)
        }
        __syncthreads();
        if (tid < TT) {
            float m = -1e30f;
            #pragma unroll 8
            for (int i = 0; i < TT; i++) m = fmaxf(m, sm.score[i]);
            sm.expv[tid] = __expf(sm.score[tid] - m);
        }
        __syncthreads();
        // ---- ctx (last row): 32 threads, channel-pair packed ----
        if (tid < 32) {
            float ssum = 0.0f;
            u64 o2 = 0;
            #pragma unroll 8
            for (int i = 0; i < TT; i++) {
                float e = sm.expv[i];
                ssum += e;
                o2 = ffma2(lds64(&sm.vbuf[i * CC + 2 * tid]), pack2(e, e), o2);
            }
            float2 o = unpack2(o2);
            float r = __fdividef(1.0f, ssum);
            float2 res; res.x = o.x * r; res.y = o.y * r;
            *reinterpret_cast<float2*>(&g_last[(size_t)s * CC + 2 * tid]) = res;
        }
    }
}

// ---------------------------------------------------------------------------
// Kernel B: MLP   last(64) -> relu(256) -> relu(128) -> 12, + output transpose
// ---------------------------------------------------------------------------
struct SmemB {
    float last[32 * CC];        // 2048
    float z1[32 * H1];          // 8192
    float z2[32 * (H2 + 1)];    // 4128 (pitch 129)
};

__global__ __launch_bounds__(256)
void mlp_kernel(const float* __restrict__ W1, const float* __restrict__ b1,
                const float* __restrict__ W2, const float* __restrict__ b2,
                const float* __restrict__ W3, const float* __restrict__ b3,
                float* __restrict__ out)
{
    extern __shared__ float smem_raw[];
    SmemB& sm = *reinterpret_cast<SmemB*>(smem_raw);
    const int tid = threadIdx.x;
    const int row0 = blockIdx.x * 32;

    for (int i = tid; i < 32 * CC; i += 256)
        sm.last[i] = g_last[(size_t)row0 * CC + i];
    __syncthreads();

    // z1 = relu(last @ W1 + b1)
    {
        const int h = tid;
        float acc[32];
        float bb = b1[h];
        #pragma unroll
        for (int r = 0; r < 32; r++) acc[r] = bb;
        for (int cin = 0; cin < CC; cin++) {
            float w = W1[cin * H1 + h];
            #pragma unroll
            for (int r = 0; r < 32; r++)
                acc[r] += sm.last[r * CC + cin] * w;
        }
        #pragma unroll
        for (int r = 0; r < 32; r++)
            sm.z1[r * H1 + h] = fmaxf(acc[r], 0.0f);
    }
    __syncthreads();

    // z2 = relu(z1 @ W2 + b2)
    {
        const int h2 = tid & 127;
        const int rg = tid >> 7;
        float acc[16];
        float bb = b2[h2];
        #pragma unroll
        for (int r = 0; r < 16; r++) acc[r] = bb;
        for (int cin = 0; cin < H1; cin++) {
            float w = W2[cin * H2 + h2];
            #pragma unroll
            for (int r = 0; r < 16; r++)
                acc[r] += sm.z1[(rg * 16 + r) * H1 + cin] * w;
        }
        #pragma unroll
        for (int r = 0; r < 16; r++)
            sm.z2[(rg * 16 + r) * (H2 + 1) + h2] = fmaxf(acc[r], 0.0f);
    }
    __syncthreads();

    // pred = z2 @ W3 + b3, scatter to out[b][0][p][n]
    for (int o = tid; o < 32 * NPRED; o += 256) {
        int r = o / NPRED;
        int p = o - r * NPRED;
        float a = b3[p];
        #pragma unroll 8
        for (int kk = 0; kk < H2; kk++)
            a += sm.z2[r * (H2 + 1) + kk] * W3[kk * NPRED + p];
        int g = row0 + r;
        int b = g >> 11;
        int n = g & 2047;
        out[((size_t)b * NPRED + p) * NN + n] = a;
    }
}

// ---------------------------------------------------------------------------
extern "C" void kernel_launch(void* const* d_in, const int* in_sizes, int n_in,
                              void* d_out, int out_size)
{
    (void)in_sizes; (void)n_in; (void)out_size;
    const float* x      = (const float*)d_in[0];
    const float* W_in   = (const float*)d_in[1];
    const float* b_in   = (const float*)d_in[2];
    const float* W_conv = (const float*)d_in[3];
    const float* b_conv = (const float*)d_in[4];
    const float* Wq     = (const float*)d_in[5];
    const float* bq     = (const float*)d_in[6];
    const float* Wk     = (const float*)d_in[7];
    const float* bk     = (const float*)d_in[8];
    const float* Wv     = (const float*)d_in[9];
    const float* bv     = (const float*)d_in[10];
    const float* W1     = (const float*)d_in[11];
    const float* b1     = (const float*)d_in[12];
    const float* W2     = (const float*)d_in[13];
    const float* b2     = (const float*)d_in[14];
    const float* W3     = (const float*)d_in[15];
    const float* b3     = (const float*)d_in[16];
    float* out = (float*)d_out;

    cudaFuncSetAttribute(fused_frontend_kernel,
                         cudaFuncAttributeMaxDynamicSharedMemorySize,
                         (int)sizeof(SmemA));
    cudaFuncSetAttribute(mlp_kernel,
                         cudaFuncAttributeMaxDynamicSharedMemorySize,
                         (int)sizeof(SmemB));

    fused_frontend_kernel<<<GRID_A, 512, sizeof(SmemA)>>>(
        x, W_in, b_in, W_conv, b_conv, Wq, bq, Wk, bk, Wv, bv);
    mlp_kernel<<<GRID_B, 256, sizeof(SmemB)>>>(W1, b1, W2, b2, W3, b3, out);
}